// round 8
// baseline (speedup 1.0000x reference)
#include <cuda_runtime.h>
#include <cuda_bf16.h>
#include <cstdint>

// ===========================================================================
// Problem constants
// ===========================================================================
#define B_      128
#define RES_    25
#define D_      512
#define C_      64
#define N_      20
#define Q_      (B_ * RES_)      // 3200
#define M_ROWS  (C_ * N_)        // 1280
#define LAM     (20.0f / 512.0f)

// ===========================================================================
// Device scratch (allocation-free)
// ===========================================================================
__device__ float g_Y[M_ROWS * Q_];         // 1280 x 3200 fp32 (Z = G X^T)
__device__ float g_V[B_ * C_];             // 128 x 64 quadform sums
__device__ int8_t g_A8h[M_ROWS * D_];      // G int8 hi/lo planes + row scales
__device__ int8_t g_A8l[M_ROWS * D_];
__device__ float  g_sa[M_ROWS];
__device__ int8_t g_B8h[Q_ * D_];          // x int8 hi/lo planes + row scales
__device__ int8_t g_B8l[Q_ * D_];
__device__ float  g_sb[Q_];

// ===========================================================================
// PTX helpers (base-target only: ldmatrix / mma.sync / cp.async)
// ===========================================================================
__device__ __forceinline__ uint32_t smem_to_u32(const void* p) {
    uint32_t a;
    asm("{ .reg .u64 t; cvta.to.shared.u64 t, %1; cvt.u32.u64 %0, t; }"
        : "=r"(a) : "l"(p));
    return a;
}

#define CP_ASYNC16(dst_u32, src_ptr) \
    asm volatile("cp.async.cg.shared.global [%0], [%1], 16;" \
        :: "r"(dst_u32), "l"(src_ptr) : "memory")
#define CP_COMMIT() asm volatile("cp.async.commit_group;" ::: "memory")
#define CP_WAIT(n)  asm volatile("cp.async.wait_group %0;" :: "n"(n) : "memory")

__device__ __forceinline__ void ldsm_x4(uint32_t r[4], uint32_t addr) {
    asm volatile("ldmatrix.sync.aligned.m8n8.x4.shared.b16 {%0,%1,%2,%3}, [%4];"
        : "=r"(r[0]), "=r"(r[1]), "=r"(r[2]), "=r"(r[3]) : "r"(addr));
}

// s8 IMMA m16n8k32, int32 accumulate
__device__ __forceinline__ void imma16832(int c[4], const uint32_t a[4],
                                          uint32_t b0, uint32_t b1) {
    asm volatile(
        "mma.sync.aligned.m16n8k32.row.col.s32.s8.s8.s32 "
        "{%0,%1,%2,%3},{%4,%5,%6,%7},{%8,%9},{%0,%1,%2,%3};"
        : "+r"(c[0]), "+r"(c[1]), "+r"(c[2]), "+r"(c[3])
        : "r"(a[0]), "r"(a[1]), "r"(a[2]), "r"(a[3]), "r"(b0), "r"(b1));
}

// ===========================================================================
// Kernel 1: per-class setup, fully fused:
//   A = H H^T + lam*I ; M = A^-1 ; S = M + lam*M^2 ; S = L L^T ;
//   G = L^T H (in place) ; per-row int8 quantization -> g_A8h/g_A8l/g_sa
// ===========================================================================
#define PAD_D 513

__global__ __launch_bounds__(256) void prep_kernel(const float* __restrict__ high) {
    const int c = blockIdx.x;
    const int t = threadIdx.x;

    __shared__ float sH[N_ * PAD_D];       // ~41 KB (H, then G in place)
    __shared__ float aug[N_][2 * N_ + 1];
    __shared__ float colk[N_];
    __shared__ float sS[N_][N_ + 1];       // S, then Cholesky L (lower)
    __shared__ float sMax[N_];

    const float* Hc = high + (size_t)c * N_ * D_;
    for (int i = t; i < N_ * D_; i += blockDim.x) {
        int r = i / D_, k = i % D_;
        sH[r * PAD_D + k] = Hc[i];
    }
    if (t < N_) sMax[t] = 0.0f;
    __syncthreads();

    // Gram + lam*I | I
    for (int e = t; e < N_ * N_; e += blockDim.x) {
        int i = e / N_, j = e % N_;
        const float* ri = sH + i * PAD_D;
        const float* rj = sH + j * PAD_D;
        float a0 = 0.f, a1 = 0.f, a2 = 0.f, a3 = 0.f;
        #pragma unroll 4
        for (int k = 0; k < D_; k += 4) {
            a0 = fmaf(ri[k + 0], rj[k + 0], a0);
            a1 = fmaf(ri[k + 1], rj[k + 1], a1);
            a2 = fmaf(ri[k + 2], rj[k + 2], a2);
            a3 = fmaf(ri[k + 3], rj[k + 3], a3);
        }
        float acc = (a0 + a1) + (a2 + a3);
        aug[i][j] = acc + (i == j ? LAM : 0.0f);
        aug[i][N_ + j] = (i == j) ? 1.0f : 0.0f;
    }
    __syncthreads();

    // Gauss-Jordan (SPD, no pivoting)
    for (int k = 0; k < N_; k++) {
        float pinv = 1.0f / aug[k][k];
        if (t < N_) colk[t] = aug[t][k];
        __syncthreads();
        if (t < 2 * N_) aug[k][t] *= pinv;
        __syncthreads();
        for (int e = t; e < N_ * 2 * N_; e += blockDim.x) {
            int i = e / (2 * N_), j = e % (2 * N_);
            if (i != k) aug[i][j] = fmaf(-colk[i], aug[k][j], aug[i][j]);
        }
        __syncthreads();
    }

    // S = M + lam * M*M
    for (int e = t; e < N_ * N_; e += blockDim.x) {
        int i = e / N_, j = e % N_;
        float acc = 0.0f;
        #pragma unroll
        for (int k = 0; k < N_; k++) acc = fmaf(aug[i][N_ + k], aug[k][N_ + j], acc);
        sS[i][j] = aug[i][N_ + j] + LAM * acc;
    }
    __syncthreads();

    // In-place Cholesky (lower): S = L L^T
    for (int k = 0; k < N_; k++) {
        if (t == 0) sS[k][k] = sqrtf(sS[k][k]);
        __syncthreads();
        if (t > k && t < N_) sS[t][k] /= sS[k][k];
        __syncthreads();
        for (int e = t; e < N_ * N_; e += blockDim.x) {
            int i = e / N_, j = e % N_;
            if (j > k && i >= j) sS[i][j] = fmaf(-sS[i][k], sS[j][k], sS[i][j]);
        }
        __syncthreads();
    }

    // G = L^T H, in place into sH (ascending i; G[i] only needs H[j], j>=i).
    // Each thread owns kd = t and t+256 for the current row i.
    for (int i = 0; i < N_; i++) {
        float v0 = 0.f, v1 = 0.f;
        const int kd0 = t, kd1 = t + 256;
        for (int j = i; j < N_; j++) {
            float lji = sS[j][i];
            v0 = fmaf(lji, sH[j * PAD_D + kd0], v0);
            v1 = fmaf(lji, sH[j * PAD_D + kd1], v1);
        }
        __syncthreads();
        sH[i * PAD_D + kd0] = v0;
        sH[i * PAD_D + kd1] = v1;
        // track row absmax (no atomics yet; do after full write)
        __syncthreads();
    }

    // Row absmax via smem atomicMax on float bits (non-negative floats).
    for (int e = t; e < N_ * D_; e += blockDim.x) {
        int i = e / D_, kd = e % D_;
        float av = fabsf(sH[i * PAD_D + kd]);
        atomicMax(reinterpret_cast<int*>(&sMax[i]), __float_as_int(av));
    }
    __syncthreads();

    // Quantize: i16 = rn(v * 8192 / s); h = (i16+64)>>7 (l in [-64,63])
    int8_t* Ah = g_A8h + (size_t)c * N_ * D_;
    int8_t* Al = g_A8l + (size_t)c * N_ * D_;
    for (int e = t; e < N_ * D_; e += blockDim.x) {
        int i = e / D_, kd = e % D_;
        float s = fmaxf(sMax[i], 1e-20f);
        int iv = __float2int_rn(sH[i * PAD_D + kd] * (8192.0f / s));
        int h = (iv + 64) >> 7;
        int l = iv - (h << 7);
        Ah[e] = (int8_t)h;
        Al[e] = (int8_t)l;
    }
    if (t < N_) g_sa[c * N_ + t] = fmaxf(sMax[t], 1e-20f);
}

// ===========================================================================
// Kernel 2: per-row int8 quantization of x.  One block per q row.
// ===========================================================================
__global__ __launch_bounds__(128) void quantx_kernel(const float* __restrict__ x) {
    const int q = blockIdx.x;
    const int t = threadIdx.x;
    const int lane = t & 31;
    const int w = t >> 5;

    __shared__ float sWmax[4];
    __shared__ float sScale;

    const float4 v = reinterpret_cast<const float4*>(x + (size_t)q * D_)[t];
    float mx = fmaxf(fmaxf(fabsf(v.x), fabsf(v.y)), fmaxf(fabsf(v.z), fabsf(v.w)));
    #pragma unroll
    for (int off = 16; off > 0; off >>= 1)
        mx = fmaxf(mx, __shfl_xor_sync(0xffffffffu, mx, off));
    if (lane == 0) sWmax[w] = mx;
    __syncthreads();
    if (t == 0) {
        float s = fmaxf(fmaxf(sWmax[0], sWmax[1]), fmaxf(sWmax[2], sWmax[3]));
        s = fmaxf(s, 1e-20f);
        sScale = s;
        g_sb[q] = s;
    }
    __syncthreads();

    const float inv = 8192.0f / sScale;
    char4 h4, l4;
    {
        int iv, h;
        iv = __float2int_rn(v.x * inv); h = (iv + 64) >> 7; h4.x = (char)h; l4.x = (char)(iv - (h << 7));
        iv = __float2int_rn(v.y * inv); h = (iv + 64) >> 7; h4.y = (char)h; l4.y = (char)(iv - (h << 7));
        iv = __float2int_rn(v.z * inv); h = (iv + 64) >> 7; h4.z = (char)h; l4.z = (char)(iv - (h << 7));
        iv = __float2int_rn(v.w * inv); h = (iv + 64) >> 7; h4.w = (char)h; l4.w = (char)(iv - (h << 7));
    }
    reinterpret_cast<char4*>(g_B8h + (size_t)q * D_)[t] = h4;
    reinterpret_cast<char4*>(g_B8l + (size_t)q * D_)[t] = l4;
}

// ===========================================================================
// Kernel 3: IMMA s8 GEMM.  Z = G_all(1280x512) * X^T, 2-word int8 split.
// Tile 128x64, K chunks of 64 int8 (2 x k32 steps), double-buffered cp.async.
// Per k32 step, 3 IMMAs per (mt,nt): hh->acc_hh, h*l + l*h -> acc_x.
// Dequant in epilogue: Y = sa*sb*(hh*2^-12 + x*2^-19).
// ===========================================================================
#define BM   128
#define BN   64
#define BKc  64                   // int8 K elements per chunk (64 bytes/row)
#define NKC  (D_ / BKc)           // 8
#define ROWB 80                   // 64B data + 16B pad
#define SZ_A (BM * ROWB)          // 10240
#define SZ_B (BN * ROWB)          // 5120
#define SA_HI 0
#define SA_LO SZ_A
#define SB_HI (2 * SZ_A)
#define SB_LO (2 * SZ_A + SZ_B)
#define STG   (2 * SZ_A + 2 * SZ_B)   // 30720 per stage
#define SM_TOTAL (2 * STG)            // 61440

__global__ __launch_bounds__(256) void gemm_kernel() {
    extern __shared__ char sm[];
    const uint32_t sb = smem_to_u32(sm);
    const int tid = threadIdx.x;
    const int lane = tid & 31;
    const int wid = tid >> 5;
    const int wm = wid & 3;
    const int wn = wid >> 2;
    const int m0 = blockIdx.y * BM;
    const int n0 = blockIdx.x * BN;

    int acc_hh[2][4][4];
    int acc_x[2][4][4];
    #pragma unroll
    for (int i = 0; i < 2; i++)
        #pragma unroll
        for (int j = 0; j < 4; j++)
            #pragma unroll
            for (int k = 0; k < 4; k++) { acc_hh[i][j][k] = 0; acc_x[i][j][k] = 0; }

    const int ar0 = tid >> 2;            // 0..63
    const int ac4 = (tid & 3) * 16;      // byte offset within 64B row chunk
    const int br  = tid >> 2;

    // ldmatrix addressing (byte-identical to the bf16 k16 layout)
    const int a_row  = wm * 32 + (lane & 15);
    const int a_kb   = (lane >> 4) * 16;                 // 0 or 16 bytes
    const uint32_t aoff = (uint32_t)(a_row * ROWB + a_kb);
    const int b_row  = wn * 32 + (lane & 7) + ((lane >> 4) * 8);
    const int b_kb   = ((lane >> 3) & 1) * 16;
    const uint32_t boff = (uint32_t)(b_row * ROWB + b_kb);

    auto load_stage = [&](int s, int kc) {
        const uint32_t base = sb + s * STG;
        const size_t kbase = (size_t)kc * BKc;
        #pragma unroll
        for (int p = 0; p < 2; p++) {
            int row = ar0 + p * 64;
            uint32_t d = base + SA_HI + row * ROWB + ac4;
            CP_ASYNC16(d, g_A8h + (size_t)(m0 + row) * D_ + kbase + ac4);
            d = base + SA_LO + row * ROWB + ac4;
            CP_ASYNC16(d, g_A8l + (size_t)(m0 + row) * D_ + kbase + ac4);
        }
        {
            uint32_t d = base + SB_HI + br * ROWB + ac4;
            CP_ASYNC16(d, g_B8h + (size_t)(n0 + br) * D_ + kbase + ac4);
            d = base + SB_LO + br * ROWB + ac4;
            CP_ASYNC16(d, g_B8l + (size_t)(n0 + br) * D_ + kbase + ac4);
        }
    };

    load_stage(0, 0); CP_COMMIT();
    load_stage(1, 1); CP_COMMIT();

    for (int kc = 0; kc < NKC; kc++) {
        const int s = kc & 1;
        if (kc + 1 < NKC) { CP_WAIT(1); } else { CP_WAIT(0); }
        __syncthreads();

        const uint32_t base = sb + s * STG;
        #pragma unroll
        for (int ks = 0; ks < 2; ks++) {
            const uint32_t kb = ks * 32;   // 32 bytes = one k32 step
            uint32_t ah0[4], ah1[4], al0[4], al1[4];
            ldsm_x4(ah0, base + SA_HI + aoff + kb);
            ldsm_x4(ah1, base + SA_HI + aoff + 16 * ROWB + kb);
            ldsm_x4(al0, base + SA_LO + aoff + kb);
            ldsm_x4(al1, base + SA_LO + aoff + 16 * ROWB + kb);

            uint32_t bh[4], bh2[4], bl[4], bl2[4];
            ldsm_x4(bh,  base + SB_HI + boff + kb);
            ldsm_x4(bh2, base + SB_HI + boff + 16 * ROWB + kb);
            ldsm_x4(bl,  base + SB_LO + boff + kb);
            ldsm_x4(bl2, base + SB_LO + boff + 16 * ROWB + kb);

            uint32_t Bh[4][2] = {{bh[0],bh[1]},{bh[2],bh[3]},{bh2[0],bh2[1]},{bh2[2],bh2[3]}};
            uint32_t Bl[4][2] = {{bl[0],bl[1]},{bl[2],bl[3]},{bl2[0],bl2[1]},{bl2[2],bl2[3]}};

            #pragma unroll
            for (int nt = 0; nt < 4; nt++) {
                imma16832(acc_hh[0][nt], ah0, Bh[nt][0], Bh[nt][1]);
                imma16832(acc_hh[1][nt], ah1, Bh[nt][0], Bh[nt][1]);
                imma16832(acc_x[0][nt],  ah0, Bl[nt][0], Bl[nt][1]);
                imma16832(acc_x[1][nt],  ah1, Bl[nt][0], Bl[nt][1]);
                imma16832(acc_x[0][nt],  al0, Bh[nt][0], Bh[nt][1]);
                imma16832(acc_x[1][nt],  al1, Bh[nt][0], Bh[nt][1]);
            }
        }
        __syncthreads();

        if (kc + 2 < NKC) { load_stage(s, kc + 2); CP_COMMIT(); }
    }

    // Epilogue: dequantize and store fp32 Z
    const int gr = lane >> 2;
    const int gc = (lane & 3) * 2;
    #pragma unroll
    for (int mt = 0; mt < 2; mt++) {
        const int r0 = m0 + wm * 32 + mt * 16 + gr;
        const float sa0 = g_sa[r0];
        const float sa1 = g_sa[r0 + 8];
        #pragma unroll
        for (int nt = 0; nt < 4; nt++) {
            const int col = n0 + wn * 32 + nt * 8 + gc;
            const float sb0 = g_sb[col];
            const float sb1 = g_sb[col + 1];
            const float k1 = 1.0f / 4096.0f;      // 2^-12
            const float k2 = 1.0f / 524288.0f;    // 2^-19
            float2 v0, v1;
            v0.x = sa0 * sb0 * ((float)acc_hh[mt][nt][0] * k1 + (float)acc_x[mt][nt][0] * k2);
            v0.y = sa0 * sb1 * ((float)acc_hh[mt][nt][1] * k1 + (float)acc_x[mt][nt][1] * k2);
            v1.x = sa1 * sb0 * ((float)acc_hh[mt][nt][2] * k1 + (float)acc_x[mt][nt][2] * k2);
            v1.y = sa1 * sb1 * ((float)acc_hh[mt][nt][3] * k1 + (float)acc_x[mt][nt][3] * k2);
            *reinterpret_cast<float2*>(g_Y + (size_t)r0 * Q_ + col) = v0;
            *reinterpret_cast<float2*>(g_Y + (size_t)(r0 + 8) * Q_ + col) = v1;
        }
    }
}

// ===========================================================================
// Kernel 4a: sum-of-squares quadforms.  V[b,c] = sum_{i,r} Z[c*20+i, b*25+r]^2
// ===========================================================================
__global__ __launch_bounds__(256) void quadv_kernel() {
    const int b  = blockIdx.x;
    const int cg = blockIdx.y;
    const int wid = threadIdx.x >> 5;
    const int lane = threadIdx.x & 31;
    const int c = cg * 8 + wid;

    float acc = 0.0f;
    if (lane < RES_) {
        const size_t q = (size_t)b * RES_ + lane;
        const float* base = g_Y + (size_t)c * N_ * Q_ + q;
        #pragma unroll
        for (int i = 0; i < N_; i++) {
            float v = base[(size_t)i * Q_];
            acc = fmaf(v, v, acc);
        }
    }
    #pragma unroll
    for (int off = 16; off > 0; off >>= 1)
        acc += __shfl_down_sync(0xffffffffu, acc, off);
    if (lane == 0) g_V[b * C_ + c] = acc;
}

// ===========================================================================
// Kernel 4b: per-b min-max scale.
// ===========================================================================
__global__ __launch_bounds__(64) void minmax_kernel(float* __restrict__ out) {
    const int b = blockIdx.x;
    const int t = threadIdx.x;
    const int lane = t & 31;
    const int w = t >> 5;

    __shared__ float sMn[2], sMx[2];

    float v = g_V[b * C_ + t];
    float mn = v, mx = v;
    #pragma unroll
    for (int off = 16; off > 0; off >>= 1) {
        mn = fminf(mn, __shfl_xor_sync(0xffffffffu, mn, off));
        mx = fmaxf(mx, __shfl_xor_sync(0xffffffffu, mx, off));
    }
    if (lane == 0) { sMn[w] = mn; sMx[w] = mx; }
    __syncthreads();
    float gmn = fminf(sMn[0], sMn[1]);
    float gmx = fmaxf(sMx[0], sMx[1]);

    out[b * C_ + t] = (v - gmn) / (gmx - gmn);
}

// ===========================================================================
extern "C" void kernel_launch(void* const* d_in, const int* in_sizes, int n_in,
                              void* d_out, int out_size) {
    const float* x    = (const float*)d_in[0];   // (128, 25, 512)
    const float* high = (const float*)d_in[1];   // (64, 20, 512)
    float* out = (float*)d_out;                  // (128, 64)

    cudaFuncSetAttribute(gemm_kernel,
                         cudaFuncAttributeMaxDynamicSharedMemorySize, SM_TOTAL);

    quantx_kernel<<<Q_, 128>>>(x);
    prep_kernel<<<C_, 256>>>(high);

    dim3 grid(Q_ / BN, M_ROWS / BM);             // (50, 10)
    gemm_kernel<<<grid, 256, SM_TOTAL>>>();

    dim3 qgrid(B_, C_ / 8);                      // (128, 8)
    quadv_kernel<<<qgrid, 256>>>();
    minmax_kernel<<<B_, 64>>>(out);
}

// round 9
// speedup vs baseline: 2.9190x; 2.9190x over previous
#include <cuda_runtime.h>
#include <cuda_bf16.h>
#include <cstdint>

// ===========================================================================
// Problem constants
// ===========================================================================
#define B_      128
#define RES_    25
#define D_      512
#define C_      64
#define N_      20
#define Q_      (B_ * RES_)      // 3200
#define M_ROWS  (C_ * N_)        // 1280
#define LAM     (20.0f / 512.0f)

// ===========================================================================
// Device scratch (allocation-free)
// ===========================================================================
__device__ float g_Y[M_ROWS * Q_];                 // 1280 x 3200 fp32 (Z = G X^T)
__device__ float g_V[B_ * C_];                     // 128 x 64 quadform sums
__device__ __nv_bfloat16 g_Ahi[M_ROWS * D_];       // G hi/lo planes (written by prep)
__device__ __nv_bfloat16 g_Alo[M_ROWS * D_];
__device__ __nv_bfloat16 g_Bhi[Q_ * D_];           // x hi/lo planes (written by convert)
__device__ __nv_bfloat16 g_Blo[Q_ * D_];

// ===========================================================================
// PTX helpers (base-target only: ldmatrix / mma.sync / cp.async)
// ===========================================================================
__device__ __forceinline__ uint32_t smem_to_u32(const void* p) {
    uint32_t a;
    asm("{ .reg .u64 t; cvta.to.shared.u64 t, %1; cvt.u32.u64 %0, t; }"
        : "=r"(a) : "l"(p));
    return a;
}

#define CP_ASYNC16(dst_u32, src_ptr) \
    asm volatile("cp.async.cg.shared.global [%0], [%1], 16;" \
        :: "r"(dst_u32), "l"(src_ptr) : "memory")
#define CP_COMMIT() asm volatile("cp.async.commit_group;" ::: "memory")
#define CP_WAIT(n)  asm volatile("cp.async.wait_group %0;" :: "n"(n) : "memory")

__device__ __forceinline__ void ldsm_x4(uint32_t r[4], uint32_t addr) {
    asm volatile("ldmatrix.sync.aligned.m8n8.x4.shared.b16 {%0,%1,%2,%3}, [%4];"
        : "=r"(r[0]), "=r"(r[1]), "=r"(r[2]), "=r"(r[3]) : "r"(addr));
}

__device__ __forceinline__ void mma16816(float c[4], const uint32_t a[4],
                                         uint32_t b0, uint32_t b1) {
    asm volatile(
        "mma.sync.aligned.m16n8k16.row.col.f32.bf16.bf16.f32 "
        "{%0,%1,%2,%3},{%4,%5,%6,%7},{%8,%9},{%0,%1,%2,%3};"
        : "+f"(c[0]), "+f"(c[1]), "+f"(c[2]), "+f"(c[3])
        : "r"(a[0]), "r"(a[1]), "r"(a[2]), "r"(a[3]), "r"(b0), "r"(b1));
}

// ===========================================================================
// Kernel 1: per-class setup (identical to the 92.7us run):
//   A = H H^T + lam*I ; M = A^-1 ; S = M + lam*M^2 ; S = L L^T ;
//   G = L^T H  ->  emitted directly as bf16 hi/lo planes
// ===========================================================================
#define PAD_D 513

__global__ __launch_bounds__(256) void prep_kernel(const float* __restrict__ high) {
    const int c = blockIdx.x;
    const int t = threadIdx.x;

    __shared__ float sH[N_ * PAD_D];
    __shared__ float aug[N_][2 * N_ + 1];
    __shared__ float colk[N_];
    __shared__ float sS[N_][N_ + 1];

    const float* Hc = high + (size_t)c * N_ * D_;
    for (int i = t; i < N_ * D_; i += blockDim.x) {
        int r = i / D_, k = i % D_;
        sH[r * PAD_D + k] = Hc[i];
    }
    __syncthreads();

    for (int e = t; e < N_ * N_; e += blockDim.x) {
        int i = e / N_, j = e % N_;
        const float* ri = sH + i * PAD_D;
        const float* rj = sH + j * PAD_D;
        float a0 = 0.f, a1 = 0.f, a2 = 0.f, a3 = 0.f;
        #pragma unroll 4
        for (int k = 0; k < D_; k += 4) {
            a0 = fmaf(ri[k + 0], rj[k + 0], a0);
            a1 = fmaf(ri[k + 1], rj[k + 1], a1);
            a2 = fmaf(ri[k + 2], rj[k + 2], a2);
            a3 = fmaf(ri[k + 3], rj[k + 3], a3);
        }
        float acc = (a0 + a1) + (a2 + a3);
        aug[i][j] = acc + (i == j ? LAM : 0.0f);
        aug[i][N_ + j] = (i == j) ? 1.0f : 0.0f;
    }
    __syncthreads();

    for (int k = 0; k < N_; k++) {
        float pinv = 1.0f / aug[k][k];
        if (t < N_) colk[t] = aug[t][k];
        __syncthreads();
        if (t < 2 * N_) aug[k][t] *= pinv;
        __syncthreads();
        for (int e = t; e < N_ * 2 * N_; e += blockDim.x) {
            int i = e / (2 * N_), j = e % (2 * N_);
            if (i != k) aug[i][j] = fmaf(-colk[i], aug[k][j], aug[i][j]);
        }
        __syncthreads();
    }

    for (int e = t; e < N_ * N_; e += blockDim.x) {
        int i = e / N_, j = e % N_;
        float acc = 0.0f;
        #pragma unroll
        for (int k = 0; k < N_; k++) acc = fmaf(aug[i][N_ + k], aug[k][N_ + j], acc);
        sS[i][j] = aug[i][N_ + j] + LAM * acc;
    }
    __syncthreads();

    for (int k = 0; k < N_; k++) {
        if (t == 0) sS[k][k] = sqrtf(sS[k][k]);
        __syncthreads();
        if (t > k && t < N_) sS[t][k] /= sS[k][k];
        __syncthreads();
        for (int e = t; e < N_ * N_; e += blockDim.x) {
            int i = e / N_, j = e % N_;
            if (j > k && i >= j) sS[i][j] = fmaf(-sS[i][k], sS[j][k], sS[i][j]);
        }
        __syncthreads();
    }

    __nv_bfloat16* Ahi = g_Ahi + (size_t)c * N_ * D_;
    __nv_bfloat16* Alo = g_Alo + (size_t)c * N_ * D_;
    for (int e = t; e < N_ * D_; e += blockDim.x) {
        int i = e / D_, kd = e % D_;
        float acc = 0.0f;
        for (int j = i; j < N_; j++)
            acc = fmaf(sS[j][i], sH[j * PAD_D + kd], acc);
        __nv_bfloat16 h = __float2bfloat16(acc);
        Ahi[e] = h;
        Alo[e] = __float2bfloat16(acc - __bfloat162float(h));
    }
}

// ===========================================================================
// Kernel 2: fp32 x -> bf16 hi/lo planes (B side only)
// ===========================================================================
__global__ __launch_bounds__(256) void convert_kernel(const float* __restrict__ x)
{
    const int NB = Q_ * D_;
    int idx = blockIdx.x * blockDim.x + threadIdx.x;
    int stride = gridDim.x * blockDim.x;
    for (int i = idx; i < NB; i += stride) {
        float v = x[i];
        __nv_bfloat16 h = __float2bfloat16(v);
        g_Bhi[i] = h;
        g_Blo[i] = __float2bfloat16(v - __bfloat162float(h));
    }
}

// ===========================================================================
// Kernel 3: HMMA bf16x3 GEMM.  Z = G_all(1280x512) * X^T.
// Tile 128x128 (BN doubled vs prior round): halves block count, halves A
// re-streaming, and halves ldsm-per-MMA.  8 warps as 4m x 2n, warp tile
// 32m x 64n (2 x 8 m16n8k16), 3 MMAs per k-step (hi*hi + lo*hi + hi*lo).
// ===========================================================================
#define BM   128
#define BN   128
#define BKc  32
#define NKC  (D_ / BKc)           // 16
#define ROWB 80                   // 64B data + 16B pad (conflict-free ldsm)
#define SZ_T (128 * ROWB)         // 10240 per plane (A and B both 128 rows)
#define SA_HI 0
#define SA_LO SZ_T
#define SB_HI (2 * SZ_T)
#define SB_LO (3 * SZ_T)
#define STG   (4 * SZ_T)          // 40960 per stage
#define SM_TOTAL (2 * STG)        // 81920

__global__ __launch_bounds__(256) void gemm_kernel() {
    extern __shared__ char sm[];
    const uint32_t sb = smem_to_u32(sm);
    const int tid = threadIdx.x;
    const int lane = tid & 31;
    const int wid = tid >> 5;
    const int wm = wid & 3;          // m offset 32*wm
    const int wn = wid >> 2;         // n offset 64*wn
    const int m0 = blockIdx.y * BM;
    const int n0 = blockIdx.x * BN;

    float acc[2][8][4];
    #pragma unroll
    for (int i = 0; i < 2; i++)
        #pragma unroll
        for (int j = 0; j < 8; j++)
            #pragma unroll
            for (int k = 0; k < 4; k++) acc[i][j][k] = 0.0f;

    const int ar0 = tid >> 2;            // 0..63
    const int ac4 = (tid & 3) * 16;      // byte offset of uint4 within 64B row
    const int ak8 = (tid & 3) * 8;       // element offset

    const int a_row  = wm * 32 + (lane & 15);
    const int a_kb   = ((lane >> 4) * 8) * 2;
    const uint32_t aoff = (uint32_t)(a_row * ROWB + a_kb);
    const int b_row  = wn * 64 + (lane & 7) + ((lane >> 4) * 8);
    const int b_kb   = (((lane >> 3) & 1) * 8) * 2;
    const uint32_t boff = (uint32_t)(b_row * ROWB + b_kb);

    auto load_stage = [&](int s, int kc) {
        const uint32_t base = sb + s * STG;
        const size_t kbase = (size_t)kc * BKc;
        #pragma unroll
        for (int p = 0; p < 2; p++) {
            int row = ar0 + p * 64;
            size_t ga = (size_t)(m0 + row) * D_ + kbase + ak8;
            size_t gb = (size_t)(n0 + row) * D_ + kbase + ak8;
            uint32_t soff = (uint32_t)(row * ROWB + ac4);
            CP_ASYNC16(base + SA_HI + soff, g_Ahi + ga);
            CP_ASYNC16(base + SA_LO + soff, g_Alo + ga);
            CP_ASYNC16(base + SB_HI + soff, g_Bhi + gb);
            CP_ASYNC16(base + SB_LO + soff, g_Blo + gb);
        }
    };

    load_stage(0, 0); CP_COMMIT();
    load_stage(1, 1); CP_COMMIT();

    for (int kc = 0; kc < NKC; kc++) {
        const int s = kc & 1;
        if (kc + 1 < NKC) { CP_WAIT(1); } else { CP_WAIT(0); }
        __syncthreads();

        const uint32_t base = sb + s * STG;
        #pragma unroll
        for (int ks = 0; ks < 2; ks++) {
            const uint32_t kb = ks * 32;   // 16 bf16 = 32 bytes
            uint32_t ah0[4], ah1[4], al0[4], al1[4];
            ldsm_x4(ah0, base + SA_HI + aoff + kb);
            ldsm_x4(ah1, base + SA_HI + aoff + 16 * ROWB + kb);
            ldsm_x4(al0, base + SA_LO + aoff + kb);
            ldsm_x4(al1, base + SA_LO + aoff + 16 * ROWB + kb);

            uint32_t Bh[8][2], Bl[8][2];
            #pragma unroll
            for (int g = 0; g < 4; g++) {
                uint32_t bh[4], bl[4];
                ldsm_x4(bh, base + SB_HI + boff + g * 16 * ROWB + kb);
                ldsm_x4(bl, base + SB_LO + boff + g * 16 * ROWB + kb);
                Bh[g * 2 + 0][0] = bh[0]; Bh[g * 2 + 0][1] = bh[1];
                Bh[g * 2 + 1][0] = bh[2]; Bh[g * 2 + 1][1] = bh[3];
                Bl[g * 2 + 0][0] = bl[0]; Bl[g * 2 + 0][1] = bl[1];
                Bl[g * 2 + 1][0] = bl[2]; Bl[g * 2 + 1][1] = bl[3];
            }

            #pragma unroll
            for (int nt = 0; nt < 8; nt++) {
                mma16816(acc[0][nt], ah0, Bh[nt][0], Bh[nt][1]);
                mma16816(acc[1][nt], ah1, Bh[nt][0], Bh[nt][1]);
                mma16816(acc[0][nt], al0, Bh[nt][0], Bh[nt][1]);
                mma16816(acc[1][nt], al1, Bh[nt][0], Bh[nt][1]);
                mma16816(acc[0][nt], ah0, Bl[nt][0], Bl[nt][1]);
                mma16816(acc[1][nt], ah1, Bl[nt][0], Bl[nt][1]);
            }
        }
        __syncthreads();

        if (kc + 2 < NKC) { load_stage(s, kc + 2); CP_COMMIT(); }
    }

    const int gr = lane >> 2;
    const int gc = (lane & 3) * 2;
    #pragma unroll
    for (int mt = 0; mt < 2; mt++) {
        const int rbase = m0 + wm * 32 + mt * 16 + gr;
        #pragma unroll
        for (int nt = 0; nt < 8; nt++) {
            const int col = n0 + wn * 64 + nt * 8 + gc;
            float2 v0 = {acc[mt][nt][0], acc[mt][nt][1]};
            float2 v1 = {acc[mt][nt][2], acc[mt][nt][3]};
            *reinterpret_cast<float2*>(g_Y + (size_t)rbase * Q_ + col) = v0;
            *reinterpret_cast<float2*>(g_Y + (size_t)(rbase + 8) * Q_ + col) = v1;
        }
    }
}

// ===========================================================================
// Kernel 4a: sum-of-squares quadforms.  V[b,c] = sum_{i,r} Z[c*20+i, b*25+r]^2
// ===========================================================================
__global__ __launch_bounds__(256) void quadv_kernel() {
    const int b  = blockIdx.x;
    const int cg = blockIdx.y;
    const int wid = threadIdx.x >> 5;
    const int lane = threadIdx.x & 31;
    const int c = cg * 8 + wid;

    float acc = 0.0f;
    if (lane < RES_) {
        const size_t q = (size_t)b * RES_ + lane;
        const float* base = g_Y + (size_t)c * N_ * Q_ + q;
        #pragma unroll
        for (int i = 0; i < N_; i++) {
            float v = base[(size_t)i * Q_];
            acc = fmaf(v, v, acc);
        }
    }
    #pragma unroll
    for (int off = 16; off > 0; off >>= 1)
        acc += __shfl_down_sync(0xffffffffu, acc, off);
    if (lane == 0) g_V[b * C_ + c] = acc;
}

// ===========================================================================
// Kernel 4b: per-b min-max scale.
// ===========================================================================
__global__ __launch_bounds__(64) void minmax_kernel(float* __restrict__ out) {
    const int b = blockIdx.x;
    const int t = threadIdx.x;
    const int lane = t & 31;
    const int w = t >> 5;

    __shared__ float sMn[2], sMx[2];

    float v = g_V[b * C_ + t];
    float mn = v, mx = v;
    #pragma unroll
    for (int off = 16; off > 0; off >>= 1) {
        mn = fminf(mn, __shfl_xor_sync(0xffffffffu, mn, off));
        mx = fmaxf(mx, __shfl_xor_sync(0xffffffffu, mx, off));
    }
    if (lane == 0) { sMn[w] = mn; sMx[w] = mx; }
    __syncthreads();
    float gmn = fminf(sMn[0], sMn[1]);
    float gmx = fmaxf(sMx[0], sMx[1]);

    out[b * C_ + t] = (v - gmn) / (gmx - gmn);
}

// ===========================================================================
extern "C" void kernel_launch(void* const* d_in, const int* in_sizes, int n_in,
                              void* d_out, int out_size) {
    const float* x    = (const float*)d_in[0];   // (128, 25, 512)
    const float* high = (const float*)d_in[1];   // (64, 20, 512)
    float* out = (float*)d_out;                  // (128, 64)

    cudaFuncSetAttribute(gemm_kernel,
                         cudaFuncAttributeMaxDynamicSharedMemorySize, SM_TOTAL);

    convert_kernel<<<1600, 256>>>(x);
    prep_kernel<<<C_, 256>>>(high);

    dim3 grid(Q_ / BN, M_ROWS / BM);             // (25, 10)
    gemm_kernel<<<grid, 256, SM_TOTAL>>>();

    dim3 qgrid(B_, C_ / 8);                      // (128, 8)
    quadv_kernel<<<qgrid, 256>>>();
    minmax_kernel<<<B_, 64>>>(out);
}